// round 3
// baseline (speedup 1.0000x reference)
#include <cuda_runtime.h>

// Problem constants
#define Bsz 1024
#define Nn  256
#define Dd  64
#define LAT 128
#define EC  32
#define KT  32              // k-tile per pass
#define NPASS (LAT / KT)    // 4
#define NTHREADS 256

// Shared memory strides (floats), padded for conflict-free access
#define SA_STRIDE 65   // A[n][d], odd stride: (n*65+d)%32 = (n+d)%32
#define SE_STRIDE 33   // Ecomm[n][e]
#define SF_STRIDE 33   // feature tile [n][kt]
#define SL_STRIDE 33   // logit tile [n][kt]
#define WF_STRIDE 34   // weight tile [d][kt], even stride for 8B-aligned pair loads
#define WA_STRIDE 34

struct SmemT {
    float sA[Nn * SA_STRIDE];     // 16640 floats : neighbor[b] (persistent)
    float sE[Nn * SE_STRIDE];     //  8448 : relu(A @ Wc + bc)  (persistent)
    float sF[Nn * SF_STRIDE];     //  8448 : relu(A @ Wf_tile + bf) per pass
    float sL[Nn * SL_STRIDE];     //  8448 : Ecomm @ Wa2_tile per pass
    float sWf[Dd * WF_STRIDE];    //  2176 : staged Wc (phase 2) then Wf tile
    float sWa[EC * WA_STRIDE];    //  1088 : staged Wa2 tile
    float sbc[EC];
    float sbf[KT];
    float sAgg[LAT];
    float sRedA[8 * 33];
    float sRedB[8 * 33];
};
// total = 45968 floats = 183872 bytes  (< 227KB dynamic smem limit)

typedef unsigned long long u64;

__device__ __forceinline__ u64 pack2(float a, float b) {
    u64 r;
    asm("mov.b64 %0, {%1, %2};" : "=l"(r) : "f"(a), "f"(b));
    return r;
}
__device__ __forceinline__ void unpack2(u64 v, float& lo, float& hi) {
    asm("mov.b64 {%0, %1}, %2;" : "=f"(lo), "=f"(hi) : "l"(v));
}
// Packed fp32x2 FMA (Blackwell FFMA2) — 2x fp32 FMA throughput vs scalar FFMA.
__device__ __forceinline__ void ffma2(u64& d, u64 a, u64 b) {
    asm("fma.rn.f32x2 %0, %1, %2, %0;" : "+l"(d) : "l"(a), "l"(b));
}

__global__ void __launch_bounds__(NTHREADS, 1)
arm_fused_kernel(const float* __restrict__ nb,   // [B,N,D]
                 const float* __restrict__ Wc,   // [D,EC]
                 const float* __restrict__ bc,   // [EC]
                 const float* __restrict__ Wf,   // [D,LAT]
                 const float* __restrict__ bf,   // [LAT]
                 const float* __restrict__ Wa,   // [3EC,LAT] (only rows EC..2EC-1 used)
                 const float* __restrict__ Wl,   // [LAT,LAT]
                 const float* __restrict__ bl,   // [LAT]
                 float* __restrict__ out)        // [B,LAT]
{
    extern __shared__ float smem_raw[];
    SmemT* S = reinterpret_cast<SmemT*>(smem_raw);

    const int t  = threadIdx.x;
    const int b  = blockIdx.x;
    const int tx = t & 7;        // k/e tile index within pass
    const int ty = t >> 3;       // n tile index (0..31)
    const int n0 = ty * 8;

    // ---------------- Phase 1: load neighbor[b] (256x64) + Wc + bc ----------------
    {
        const float4* nb4 = reinterpret_cast<const float4*>(nb + (size_t)b * Nn * Dd);
        #pragma unroll
        for (int r = 0; r < 16; ++r) {
            int fi = t + r * NTHREADS;          // float4 index, 0..4095
            int n  = fi >> 4;                   // 16 float4 per row
            int dq = fi & 15;
            float4 v = nb4[fi];
            float* dst = &S->sA[n * SA_STRIDE + dq * 4];
            dst[0] = v.x; dst[1] = v.y; dst[2] = v.z; dst[3] = v.w;
        }
        // Wc (64x32) into sWf buffer
        #pragma unroll
        for (int r = 0; r < 8; ++r) {
            int li = t + r * NTHREADS;          // 0..2047
            int d  = li >> 5;
            int e  = li & 31;
            S->sWf[d * WF_STRIDE + e] = Wc[d * EC + e];
        }
        if (t < EC) S->sbc[t] = bc[t];
    }
    __syncthreads();

    // ---------------- Phase 2: Ecomm = relu(A @ Wc + bc)  [256 x 32] ----------------
    {
        const int e0 = tx * 4;
        u64 acc[8][2];
        #pragma unroll
        for (int i = 0; i < 8; ++i) { acc[i][0] = 0ull; acc[i][1] = 0ull; }

        #pragma unroll 8
        for (int d = 0; d < Dd; ++d) {
            u64 w0 = *reinterpret_cast<const u64*>(&S->sWf[d * WF_STRIDE + e0]);
            u64 w1 = *reinterpret_cast<const u64*>(&S->sWf[d * WF_STRIDE + e0 + 2]);
            #pragma unroll
            for (int i = 0; i < 8; ++i) {
                float a = S->sA[(n0 + i) * SA_STRIDE + d];
                u64 pa = pack2(a, a);
                ffma2(acc[i][0], pa, w0);
                ffma2(acc[i][1], pa, w1);
            }
        }
        float b0 = S->sbc[e0], b1 = S->sbc[e0 + 1], b2 = S->sbc[e0 + 2], b3 = S->sbc[e0 + 3];
        #pragma unroll
        for (int i = 0; i < 8; ++i) {
            float v0, v1, v2, v3;
            unpack2(acc[i][0], v0, v1);
            unpack2(acc[i][1], v2, v3);
            float* dst = &S->sE[(n0 + i) * SE_STRIDE + e0];
            dst[0] = fmaxf(v0 + b0, 0.f);
            dst[1] = fmaxf(v1 + b1, 0.f);
            dst[2] = fmaxf(v2 + b2, 0.f);
            dst[3] = fmaxf(v3 + b3, 0.f);
        }
    }
    __syncthreads();

    // ---------------- Phase 3: 4 passes over LAT in tiles of 32 ----------------
    const int kq = t & 31;       // softmax: column within tile
    const int g  = t >> 5;       // softmax: n-group (== warp id)

    for (int kp = 0; kp < NPASS; ++kp) {
        const int k0 = kp * KT;

        // 3a: stage Wf tile (64x32), Wa2 tile (32x32), bf tile
        #pragma unroll
        for (int r = 0; r < 8; ++r) {
            int li = t + r * NTHREADS;
            int d  = li >> 5;
            int kt = li & 31;
            S->sWf[d * WF_STRIDE + kt] = Wf[d * LAT + k0 + kt];
        }
        #pragma unroll
        for (int r = 0; r < 4; ++r) {
            int li = t + r * NTHREADS;
            int e  = li >> 5;
            int kt = li & 31;
            S->sWa[e * WA_STRIDE + kt] = Wa[(EC + e) * LAT + k0 + kt];
        }
        if (t < KT) S->sbf[t] = bf[k0 + t];
        __syncthreads();

        // 3b: F tile = relu(A @ Wf_tile + bf)   [256 x 32]
        {
            const int kt0 = tx * 4;
            u64 acc[8][2];
            #pragma unroll
            for (int i = 0; i < 8; ++i) { acc[i][0] = 0ull; acc[i][1] = 0ull; }

            #pragma unroll 8
            for (int d = 0; d < Dd; ++d) {
                u64 w0 = *reinterpret_cast<const u64*>(&S->sWf[d * WF_STRIDE + kt0]);
                u64 w1 = *reinterpret_cast<const u64*>(&S->sWf[d * WF_STRIDE + kt0 + 2]);
                #pragma unroll
                for (int i = 0; i < 8; ++i) {
                    float a = S->sA[(n0 + i) * SA_STRIDE + d];
                    u64 pa = pack2(a, a);
                    ffma2(acc[i][0], pa, w0);
                    ffma2(acc[i][1], pa, w1);
                }
            }
            float b0 = S->sbf[kt0], b1 = S->sbf[kt0 + 1], b2 = S->sbf[kt0 + 2], b3 = S->sbf[kt0 + 3];
            #pragma unroll
            for (int i = 0; i < 8; ++i) {
                float v0, v1, v2, v3;
                unpack2(acc[i][0], v0, v1);
                unpack2(acc[i][1], v2, v3);
                float* dst = &S->sF[(n0 + i) * SF_STRIDE + kt0];
                dst[0] = fmaxf(v0 + b0, 0.f);
                dst[1] = fmaxf(v1 + b1, 0.f);
                dst[2] = fmaxf(v2 + b2, 0.f);
                dst[3] = fmaxf(v3 + b3, 0.f);
            }
        }

        // 3c: L tile = Ecomm @ Wa2_tile   [256 x 32]  (bias/self/mean cancel in softmax)
        {
            const int kt0 = tx * 4;
            u64 acc[8][2];
            #pragma unroll
            for (int i = 0; i < 8; ++i) { acc[i][0] = 0ull; acc[i][1] = 0ull; }

            #pragma unroll 8
            for (int e = 0; e < EC; ++e) {
                u64 w0 = *reinterpret_cast<const u64*>(&S->sWa[e * WA_STRIDE + kt0]);
                u64 w1 = *reinterpret_cast<const u64*>(&S->sWa[e * WA_STRIDE + kt0 + 2]);
                #pragma unroll
                for (int i = 0; i < 8; ++i) {
                    float a = S->sE[(n0 + i) * SE_STRIDE + e];
                    u64 pa = pack2(a, a);
                    ffma2(acc[i][0], pa, w0);
                    ffma2(acc[i][1], pa, w1);
                }
            }
            #pragma unroll
            for (int i = 0; i < 8; ++i) {
                float v0, v1, v2, v3;
                unpack2(acc[i][0], v0, v1);
                unpack2(acc[i][1], v2, v3);
                float* dst = &S->sL[(n0 + i) * SL_STRIDE + kt0];
                dst[0] = v0; dst[1] = v1; dst[2] = v2; dst[3] = v3;
            }
        }
        __syncthreads();

        // 3d: per-column softmax over n (256) + weighted sum against F
        {
            float lv[32];
            float m = -1e30f;
            #pragma unroll
            for (int i = 0; i < 32; ++i) {
                lv[i] = S->sL[(g * 32 + i) * SL_STRIDE + kq];
                m = fmaxf(m, lv[i]);
            }
            S->sRedA[g * 33 + kq] = m;
            __syncthreads();
            #pragma unroll
            for (int j = 0; j < 8; ++j) m = fmaxf(m, S->sRedA[j * 33 + kq]);

            float s = 0.f, w = 0.f;
            #pragma unroll
            for (int i = 0; i < 32; ++i) {
                float e = __expf(lv[i] - m);
                s += e;
                w += e * S->sF[(g * 32 + i) * SF_STRIDE + kq];
            }
            __syncthreads();   // all reads of sRedA done before rewrite
            S->sRedA[g * 33 + kq] = s;
            S->sRedB[g * 33 + kq] = w;
            __syncthreads();
            if (g == 0) {
                float St = 0.f, Wt = 0.f;
                #pragma unroll
                for (int j = 0; j < 8; ++j) {
                    St += S->sRedA[j * 33 + kq];
                    Wt += S->sRedB[j * 33 + kq];
                }
                S->sAgg[k0 + kq] = Wt / St;
            }
            __syncthreads();   // guard sF/sL/sWf reuse next pass + sAgg visibility
        }
    }

    // ---------------- Phase 4: out[b] = relu(agg @ Wl + bl) ----------------
    if (t < LAT) {
        float acc = __ldg(&bl[t]);
        #pragma unroll 8
        for (int j = 0; j < LAT; ++j)
            acc = fmaf(S->sAgg[j], __ldg(&Wl[j * LAT + t]), acc);
        out[(size_t)b * LAT + t] = fmaxf(acc, 0.f);
    }
}

extern "C" void kernel_launch(void* const* d_in, const int* in_sizes, int n_in,
                              void* d_out, int out_size) {
    // metadata order: local_data, neighbor_data, Wc, bc, Wf, bf, Wa, ba, Wl, bl
    // local_data and ba are provably unused (softmax shift invariance over n).
    const float* nb = (const float*)d_in[1];
    const float* Wc = (const float*)d_in[2];
    const float* bc = (const float*)d_in[3];
    const float* Wf = (const float*)d_in[4];
    const float* bf = (const float*)d_in[5];
    const float* Wa = (const float*)d_in[6];
    const float* Wl = (const float*)d_in[8];
    const float* bl = (const float*)d_in[9];
    float* out = (float*)d_out;

    cudaFuncSetAttribute(arm_fused_kernel,
                         cudaFuncAttributeMaxDynamicSharedMemorySize,
                         (int)sizeof(SmemT));
    arm_fused_kernel<<<Bsz, NTHREADS, sizeof(SmemT)>>>(nb, Wc, bc, Wf, bf, Wa, Wl, bl, out);
}